// round 3
// baseline (speedup 1.0000x reference)
#include <cuda_runtime.h>

// Problem constants (fixed by the dataset)
#define B_  4
#define T_  2048
#define NH_ 8
#define N_  64
#define D_  128
#define C_  128          // chunk length
#define NC_ 16           // T_/C_
#define OUT_ELEMS (B_*T_*NH_*D_)   // 8,388,608
#define ST_ELEMS  (B_*NH_*N_*D_)   // 262,144

// Scratch: per-chunk delta-state, later overwritten by exclusive prefix.
// [B*NH][NC][N][D]
__device__ float g_dS[(size_t)B_*NH_*NC_*N_*D_];

// ---------------------------------------------------------------------------
// packed f32x2 helpers (Blackwell sm_103a)
// ---------------------------------------------------------------------------
__device__ __forceinline__ void fma2(unsigned long long& d,
                                     unsigned long long a,
                                     unsigned long long b) {
    asm("fma.rn.f32x2 %0, %1, %2, %0;" : "+l"(d) : "l"(a), "l"(b));
}
__device__ __forceinline__ float hadd2(unsigned long long v) {
    float x, y;
    asm("mov.b64 {%0, %1}, %2;" : "=f"(x), "=f"(y) : "l"(v));
    return x + y;
}

// ---------------------------------------------------------------------------
// Kernel A: dS[b,h,k][n][d] = sum_c Q[b, kC+c, h, n] * V[b, kC+c, d]
// grid = B*NH*NC = 512 blocks, 256 threads.
// Both operands stored c-transposed in smem so f32x2 pairs run along c.
// ---------------------------------------------------------------------------
#define KA_SMEM ((64 + 128) * 132 * 4)

__global__ __launch_bounds__(256, 1) void kA(const float* __restrict__ Q,
                                             const float* __restrict__ V) {
    extern __shared__ float s[];
    float* Qt = s;              // [64][132]   Qt[n][c]
    float* Vt = s + 64 * 132;   // [128][132]  Vt[d][c]

    const int tid = threadIdx.x;
    const int blk = blockIdx.x;
    const int k = blk % NC_, bh = blk / NC_;
    const int b = bh / NH_, h = bh % NH_;

    const float* Qb = Q + ((size_t)(b * T_ + k * C_) * NH_ + h) * N_;
    const float* Vb = V + (size_t)(b * T_ + k * C_) * D_;

    // Load Q chunk [C_ x N_] transposed into Qt[n][c]
#pragma unroll
    for (int it = 0; it < 8; it++) {
        int idx = tid + it * 256;           // 2048 float4s
        int c = idx >> 4, n4 = idx & 15;
        float4 q = *(const float4*)(Qb + (size_t)c * NH_ * N_ + n4 * 4);
        Qt[(n4 * 4 + 0) * 132 + c] = q.x;
        Qt[(n4 * 4 + 1) * 132 + c] = q.y;
        Qt[(n4 * 4 + 2) * 132 + c] = q.z;
        Qt[(n4 * 4 + 3) * 132 + c] = q.w;
    }
    // Load V chunk [C_ x D_] transposed into Vt[d][c]
#pragma unroll
    for (int it = 0; it < 16; it++) {
        int idx = tid + it * 256;           // 4096 float4s
        int c = idx >> 5, d4 = idx & 31;
        float4 v = *(const float4*)(Vb + (size_t)c * D_ + d4 * 4);
        Vt[(d4 * 4 + 0) * 132 + c] = v.x;
        Vt[(d4 * 4 + 1) * 132 + c] = v.y;
        Vt[(d4 * 4 + 2) * 132 + c] = v.z;
        Vt[(d4 * 4 + 3) * 132 + c] = v.w;
    }
    __syncthreads();

    const int ty = tid >> 4, tx = tid & 15;
    unsigned long long acc[4][8];
#pragma unroll
    for (int i = 0; i < 4; i++)
#pragma unroll
        for (int j = 0; j < 8; j++) acc[i][j] = 0ULL;

#pragma unroll 4
    for (int cc = 0; cc < C_; cc += 4) {
        ulonglong2 a[4];
#pragma unroll
        for (int i = 0; i < 4; i++)
            a[i] = *(const ulonglong2*)&Qt[(ty + 16 * i) * 132 + cc];
#pragma unroll
        for (int j = 0; j < 8; j++) {
            ulonglong2 bb = *(const ulonglong2*)&Vt[(tx + 16 * j) * 132 + cc];
#pragma unroll
            for (int i = 0; i < 4; i++) {
                fma2(acc[i][j], a[i].x, bb.x);
                fma2(acc[i][j], a[i].y, bb.y);
            }
        }
    }

    float* outp = g_dS + (size_t)blk * (N_ * D_);
#pragma unroll
    for (int i = 0; i < 4; i++)
#pragma unroll
        for (int j = 0; j < 8; j++)
            outp[(ty + 16 * i) * D_ + (tx + 16 * j)] = hadd2(acc[i][j]);
}

// ---------------------------------------------------------------------------
// Kernel B: in-place exclusive prefix over the 16 chunks; writes new_state.
// 262144 threads, each owns one (bh, n, d) element.
// ---------------------------------------------------------------------------
__global__ void kB(const float* __restrict__ state, float* __restrict__ out_state) {
    int gid = blockIdx.x * 256 + threadIdx.x;      // < 262144
    int bh = gid >> 13;                            // / 8192
    int e  = gid & 8191;
    float* p = g_dS + (size_t)bh * NC_ * 8192 + e;
    float run = 0.f;
#pragma unroll
    for (int k = 0; k < NC_; k++) {
        float v = p[(size_t)k * 8192];
        p[(size_t)k * 8192] = run;                 // exclusive prefix
        run += v;
    }
    if (out_state) out_state[gid] = state[gid] + run;   // new_state
}

// ---------------------------------------------------------------------------
// Kernel C: per chunk:
//   scores = tril(Q_k Q_kᵀ, -1)                         (128x128)
//   out_k  = Q_k @ (state + prefix_k)  +  scores @ V_k  (128x128)
// grid = 512 blocks, 256 threads, 8x8 tile/thread, f32x2 along reduction dim.
// ---------------------------------------------------------------------------
#define KC_SMEM ((128*68 + 128*68 + 128*132 + 128*132) * 4)   // 204,800 B

__global__ __launch_bounds__(256, 1) void kC(const float* __restrict__ Q,
                                             const float* __restrict__ V,
                                             const float* __restrict__ state,
                                             float* __restrict__ out) {
    extern __shared__ float s[];
    float* Qs = s;                    // [128][68]   Qs[t][n]
    float* St = Qs + 128 * 68;        // [128][68]   St[d][n]  (state+prefix, transposed)
    float* Vt = St + 128 * 68;        // [128][132]  Vt[d][u]
    float* Sc = Vt + 128 * 132;       // [128][132]  Sc[t][u]  (masked scores)

    const int tid = threadIdx.x;
    const int blk = blockIdx.x;
    const int k = blk % NC_, bh = blk / NC_;
    const int b = bh / NH_, h = bh % NH_;

    const float* Qb  = Q + ((size_t)(b * T_ + k * C_) * NH_ + h) * N_;
    const float* Vb  = V + (size_t)(b * T_ + k * C_) * D_;
    const float* Stb = state + (size_t)bh * N_ * D_;
    const float* dSb = g_dS + (size_t)blk * (N_ * D_);

    // Qs direct [t][n]
#pragma unroll
    for (int it = 0; it < 8; it++) {
        int idx = tid + it * 256;           // 2048 float4s
        int t = idx >> 4, n4 = idx & 15;
        *(float4*)&Qs[t * 68 + n4 * 4] =
            *(const float4*)(Qb + (size_t)t * NH_ * N_ + n4 * 4);
    }
    // Vt transposed [d][u]
#pragma unroll
    for (int it = 0; it < 16; it++) {
        int idx = tid + it * 256;           // 4096 float4s
        int u = idx >> 5, d4 = idx & 31;
        float4 v = *(const float4*)(Vb + (size_t)u * D_ + d4 * 4);
        Vt[(d4 * 4 + 0) * 132 + u] = v.x;
        Vt[(d4 * 4 + 1) * 132 + u] = v.y;
        Vt[(d4 * 4 + 2) * 132 + u] = v.z;
        Vt[(d4 * 4 + 3) * 132 + u] = v.w;
    }
    // St transposed [d][n] = state + exclusive prefix
#pragma unroll
    for (int it = 0; it < 8; it++) {
        int idx = tid + it * 256;           // 2048 float4s
        int n = idx >> 5, d4 = idx & 31;
        float4 sv = *(const float4*)(Stb + (size_t)n * D_ + d4 * 4);
        float4 dv = *(const float4*)(dSb + (size_t)n * D_ + d4 * 4);
        St[(d4 * 4 + 0) * 68 + n] = sv.x + dv.x;
        St[(d4 * 4 + 1) * 68 + n] = sv.y + dv.y;
        St[(d4 * 4 + 2) * 68 + n] = sv.z + dv.z;
        St[(d4 * 4 + 3) * 68 + n] = sv.w + dv.w;
    }
    __syncthreads();

    const int ty = tid >> 4, tx = tid & 15;

    // ---- Phase 1: scores[t][u] = Q_t . Q_u, strictly-lower mask ----
    unsigned long long acc[8][8];
#pragma unroll
    for (int i = 0; i < 8; i++)
#pragma unroll
        for (int j = 0; j < 8; j++) acc[i][j] = 0ULL;

#pragma unroll 4
    for (int nn = 0; nn < N_; nn += 4) {
        ulonglong2 a[8];
#pragma unroll
        for (int i = 0; i < 8; i++)
            a[i] = *(const ulonglong2*)&Qs[(ty + 16 * i) * 68 + nn];
#pragma unroll
        for (int j = 0; j < 8; j++) {
            ulonglong2 bb = *(const ulonglong2*)&Qs[(tx + 16 * j) * 68 + nn];
#pragma unroll
            for (int i = 0; i < 8; i++) {
                fma2(acc[i][j], a[i].x, bb.x);
                fma2(acc[i][j], a[i].y, bb.y);
            }
        }
    }
#pragma unroll
    for (int i = 0; i < 8; i++) {
        int t = ty + 16 * i;
#pragma unroll
        for (int j = 0; j < 8; j++) {
            int u = tx + 16 * j;
            Sc[t * 132 + u] = (u < t) ? hadd2(acc[i][j]) : 0.f;
        }
    }
    __syncthreads();

    // ---- Phase 2: out[t][d] = Qs[t][:]@St[d][:] + Sc[t][:]@Vt[d][:] ----
#pragma unroll
    for (int i = 0; i < 8; i++)
#pragma unroll
        for (int j = 0; j < 8; j++) acc[i][j] = 0ULL;

#pragma unroll 4
    for (int nn = 0; nn < N_; nn += 4) {
        ulonglong2 a[8];
#pragma unroll
        for (int i = 0; i < 8; i++)
            a[i] = *(const ulonglong2*)&Qs[(ty + 16 * i) * 68 + nn];
#pragma unroll
        for (int j = 0; j < 8; j++) {
            ulonglong2 bb = *(const ulonglong2*)&St[(tx + 16 * j) * 68 + nn];
#pragma unroll
            for (int i = 0; i < 8; i++) {
                fma2(acc[i][j], a[i].x, bb.x);
                fma2(acc[i][j], a[i].y, bb.y);
            }
        }
    }
#pragma unroll 4
    for (int uu = 0; uu < C_; uu += 4) {
        ulonglong2 a[8];
#pragma unroll
        for (int i = 0; i < 8; i++)
            a[i] = *(const ulonglong2*)&Sc[(ty + 16 * i) * 132 + uu];
#pragma unroll
        for (int j = 0; j < 8; j++) {
            ulonglong2 bb = *(const ulonglong2*)&Vt[(tx + 16 * j) * 132 + uu];
#pragma unroll
            for (int i = 0; i < 8; i++) {
                fma2(acc[i][j], a[i].x, bb.x);
                fma2(acc[i][j], a[i].y, bb.y);
            }
        }
    }

    float* ob = out + ((size_t)(b * T_ + k * C_) * NH_ + h) * D_;
#pragma unroll
    for (int i = 0; i < 8; i++) {
        int t = ty + 16 * i;
#pragma unroll
        for (int j = 0; j < 8; j++)
            ob[(size_t)t * NH_ * D_ + (tx + 16 * j)] = hadd2(acc[i][j]);
    }
}

// ---------------------------------------------------------------------------
extern "C" void kernel_launch(void* const* d_in, const int* in_sizes, int n_in,
                              void* d_out, int out_size) {
    const float* Q     = (const float*)d_in[0];
    const float* V     = (const float*)d_in[1];
    const float* state = (const float*)d_in[2];
    float* out = (float*)d_out;

    cudaFuncSetAttribute(kA, cudaFuncAttributeMaxDynamicSharedMemorySize, KA_SMEM);
    cudaFuncSetAttribute(kC, cudaFuncAttributeMaxDynamicSharedMemorySize, KC_SMEM);

    bool write_state = (out_size >= (OUT_ELEMS + ST_ELEMS));
    float* out_state = write_state ? (out + OUT_ELEMS) : nullptr;

    kA<<<B_ * NH_ * NC_, 256, KA_SMEM>>>(Q, V);
    kB<<<ST_ELEMS / 256, 256>>>(state, out_state);
    kC<<<B_ * NH_ * NC_, 256, KC_SMEM>>>(Q, V, state, out);
}

// round 5
// speedup vs baseline: 2.4745x; 2.4745x over previous
#include <cuda_runtime.h>
#include <cuda_bf16.h>
#include <cstdint>

// Problem constants (fixed by the dataset)
#define B_  4
#define T_  2048
#define NH_ 8
#define N_  64
#define D_  128
#define C_  128          // chunk length
#define NC_ 16           // T_/C_
#define OUT_ELEMS (B_*T_*NH_*D_)   // 8,388,608
#define ST_ELEMS  (B_*NH_*N_*D_)   // 262,144

// Scratch:
//  g_dS        : per-chunk delta-state, layout [bh*16+k][d][n] fp32
//  g_sph/g_spl : prefix state (state + sum_{j<k} dS_j), bf16 hi/lo planes, [blk][d][n]
__device__ float         g_dS [(size_t)512*8192];
__device__ __nv_bfloat16 g_sph[(size_t)512*8192];
__device__ __nv_bfloat16 g_spl[(size_t)512*8192];

// ---------------------------------------------------------------------------
// helpers
// ---------------------------------------------------------------------------
__device__ __forceinline__ uint32_t smem_u32(const void* p) {
    uint32_t a;
    asm("{ .reg .u64 t; cvta.to.shared.u64 t, %1; cvt.u32.u64 %0, t; }"
        : "=r"(a) : "l"(p));
    return a;
}
__device__ __forceinline__ void ldmx4(uint32_t* r, uint32_t a) {
    asm volatile("ldmatrix.sync.aligned.m8n8.x4.shared.b16 {%0,%1,%2,%3}, [%4];"
                 : "=r"(r[0]), "=r"(r[1]), "=r"(r[2]), "=r"(r[3]) : "r"(a));
}
__device__ __forceinline__ void ldmx2(uint32_t* r, uint32_t a) {
    asm volatile("ldmatrix.sync.aligned.m8n8.x2.shared.b16 {%0,%1}, [%2];"
                 : "=r"(r[0]), "=r"(r[1]) : "r"(a));
}
// D += A * B, m16n8k16, row.col, bf16 in / fp32 accum
__device__ __forceinline__ void mma(float* d, const uint32_t* a, const uint32_t* b) {
    asm volatile("mma.sync.aligned.m16n8k16.row.col.f32.bf16.bf16.f32 "
                 "{%0,%1,%2,%3}, {%4,%5,%6,%7}, {%8,%9}, {%0,%1,%2,%3};"
                 : "+f"(d[0]), "+f"(d[1]), "+f"(d[2]), "+f"(d[3])
                 : "r"(a[0]), "r"(a[1]), "r"(a[2]), "r"(a[3]),
                   "r"(b[0]), "r"(b[1]));
}
// fp32 pair -> packed bf16x2 hi plane + residual lo plane (a in low half)
__device__ __forceinline__ void split2(float a, float b, uint32_t& hi, uint32_t& lo) {
    __nv_bfloat16 ha = __float2bfloat16_rn(a);
    __nv_bfloat16 hb = __float2bfloat16_rn(b);
    __nv_bfloat16 la = __float2bfloat16_rn(a - __bfloat162float(ha));
    __nv_bfloat16 lb = __float2bfloat16_rn(b - __bfloat162float(hb));
    hi = (uint32_t)__bfloat16_as_ushort(ha) | ((uint32_t)__bfloat16_as_ushort(hb) << 16);
    lo = (uint32_t)__bfloat16_as_ushort(la) | ((uint32_t)__bfloat16_as_ushort(lb) << 16);
}

// padded row strides (elements): conflict-free ldmatrix (row step = 4 banks)
#define S64  72     // rows holding 64 bf16
#define S128 136    // rows holding 128 bf16

// ============================================================================
// Kernel A: dS^T[d][n] = sum_c V[c][d] * Q[c][n]
//   A = V^T [d=128 rows][c=128]  (hi/lo planes, stride S128)
//   B = Q^T [n= 64 rows][c=128]
// grid = 512 (bh*16+k), 256 threads (8 warps, 16 d-rows each)
// ============================================================================
#define KA_SMEM ((size_t)(128+128+64+64)*S128*2)   // 104,448 B

__global__ __launch_bounds__(256) void kA(const float* __restrict__ Q,
                                          const float* __restrict__ V) {
    extern __shared__ __nv_bfloat16 sm[];
    __nv_bfloat16* Vh = sm;                 // [128][S128]
    __nv_bfloat16* Vl = Vh + 128 * S128;
    __nv_bfloat16* Qh = Vl + 128 * S128;    // [64][S128]
    __nv_bfloat16* Ql = Qh + 64 * S128;

    const int tid = threadIdx.x, w = tid >> 5, L = tid & 31;
    const int blk = blockIdx.x;
    const int k = blk & 15, bh = blk >> 4;
    const int b = bh >> 3, h = bh & 7;

    const float* Qb = Q + ((size_t)(b * T_ + k * C_) * NH_ + h) * N_;
    const float* Vb = V + (size_t)(b * T_ + k * C_) * D_;

    // Q^T: [n][c] pairs along c
#pragma unroll
    for (int it = 0; it < 16; it++) {
        int idx = tid + it * 256;                 // 4096
        int n = idx & 63, c2 = idx >> 6;
        float f0 = Qb[(size_t)(2 * c2)     * (NH_ * N_) + n];
        float f1 = Qb[(size_t)(2 * c2 + 1) * (NH_ * N_) + n];
        uint32_t hi, lo; split2(f0, f1, hi, lo);
        *(uint32_t*)(Qh + n * S128 + 2 * c2) = hi;
        *(uint32_t*)(Ql + n * S128 + 2 * c2) = lo;
    }
    // V^T: [d][c] pairs along c
#pragma unroll
    for (int it = 0; it < 32; it++) {
        int idx = tid + it * 256;                 // 8192
        int d = idx & 127, c2 = idx >> 7;
        float f0 = Vb[(size_t)(2 * c2)     * D_ + d];
        float f1 = Vb[(size_t)(2 * c2 + 1) * D_ + d];
        uint32_t hi, lo; split2(f0, f1, hi, lo);
        *(uint32_t*)(Vh + d * S128 + 2 * c2) = hi;
        *(uint32_t*)(Vl + d * S128 + 2 * c2) = lo;
    }
    __syncthreads();

    const int Lm = L & 15;
    const uint32_t aA = smem_u32(Vh + (16 * w + Lm) * S128 + ((L >> 4) << 3));
    const uint32_t aB = smem_u32(Qh + (Lm & 7) * S128 + ((Lm >> 3) << 3));
    const uint32_t AOFF = 128 * S128 * 2;   // Vh -> Vl (bytes)
    const uint32_t BOFF = 64  * S128 * 2;   // Qh -> Ql

    float acc[8][4];
#pragma unroll
    for (int j = 0; j < 8; j++)
#pragma unroll
        for (int q = 0; q < 4; q++) acc[j][q] = 0.f;

#pragma unroll
    for (int kk = 0; kk < 8; kk++) {
        uint32_t ah[4], al[4];
        ldmx4(ah, aA + kk * 32);
        ldmx4(al, aA + AOFF + kk * 32);
#pragma unroll
        for (int j = 0; j < 8; j++) {
            uint32_t bhr[2], blr[2];
            uint32_t ab = aB + j * (8 * S128 * 2) + kk * 32;
            ldmx2(bhr, ab);
            ldmx2(blr, ab + BOFF);
            mma(acc[j], ah, bhr);
            mma(acc[j], ah, blr);
            mma(acc[j], al, bhr);
        }
    }

    const int r0 = 16 * w + (L >> 2);
    const int cc = (L & 3) * 2;
    float* op = g_dS + (size_t)blk * 8192;
#pragma unroll
    for (int j = 0; j < 8; j++) {
        *(float2*)(op + (size_t)r0 * 64 + 8 * j + cc)       = make_float2(acc[j][0], acc[j][1]);
        *(float2*)(op + (size_t)(r0 + 8) * 64 + 8 * j + cc) = make_float2(acc[j][2], acc[j][3]);
    }
}

// ============================================================================
// Kernel B: exclusive prefix over the 16 chunks -> bf16 hi/lo planes + new_state
// ============================================================================
__global__ void kB(const float* __restrict__ state, float* __restrict__ out_state) {
    int gid = blockIdx.x * 256 + threadIdx.x;       // < 262144
    int bh = gid >> 13, dn = gid & 8191;
    int d = dn >> 6, n = dn & 63;
    const size_t base = (size_t)bh * NC_ * 8192 + dn;
    float run = state[((size_t)bh * 64 + n) * 128 + d];
#pragma unroll
    for (int k = 0; k < NC_; k++) {
        float v = g_dS[base + (size_t)k * 8192];
        __nv_bfloat16 hh = __float2bfloat16_rn(run);
        __nv_bfloat16 ll = __float2bfloat16_rn(run - __bfloat162float(hh));
        g_sph[base + (size_t)k * 8192] = hh;
        g_spl[base + (size_t)k * 8192] = ll;
        run += v;
    }
    if (out_state) out_state[((size_t)bh * 64 + n) * 128 + d] = run;
}

// ============================================================================
// Kernel C: per chunk:
//   scores = tril(Q Q^T, -1)   (register accum, masked, reused as A frags)
//   out    = Q @ Spref + scores @ V
// grid = 512 blocks, 256 threads (8 warps, 16 t-rows each)
// ============================================================================
#define KC_SMEM ((size_t)(4*128*S64 + 2*128*S128)*2)   // 143,360 B

__global__ __launch_bounds__(256) void kC(const float* __restrict__ Q,
                                          const float* __restrict__ V,
                                          float* __restrict__ out) {
    extern __shared__ __nv_bfloat16 sm[];
    __nv_bfloat16* Qh = sm;                 // [128][S64]  Q[t][n]
    __nv_bfloat16* Ql = Qh + 128 * S64;
    __nv_bfloat16* Sh = Ql + 128 * S64;     // [128][S64]  Spref^T[d][n]
    __nv_bfloat16* Sl = Sh + 128 * S64;
    __nv_bfloat16* Vh = Sl + 128 * S64;     // [128][S128] V^T[d][u]
    __nv_bfloat16* Vl = Vh + 128 * S128;

    const int tid = threadIdx.x, w = tid >> 5, L = tid & 31;
    const int blk = blockIdx.x;
    const int k = blk & 15, bh = blk >> 4;
    const int b = bh >> 3, h = bh & 7;

    const float* Qb = Q + ((size_t)(b * T_ + k * C_) * NH_ + h) * N_;
    const float* Vb = V + (size_t)(b * T_ + k * C_) * D_;

    // Q natural [t][n], float4 loads, pairs along n
#pragma unroll
    for (int it = 0; it < 8; it++) {
        int idx = tid + it * 256;                 // 2048
        int n4 = idx & 15, t = idx >> 4;
        float4 q = *(const float4*)(Qb + (size_t)t * (NH_ * N_) + n4 * 4);
        uint32_t h0, l0, h1, l1;
        split2(q.x, q.y, h0, l0);
        split2(q.z, q.w, h1, l1);
        *(uint2*)(Qh + t * S64 + n4 * 4) = make_uint2(h0, h1);
        *(uint2*)(Ql + t * S64 + n4 * 4) = make_uint2(l0, l1);
    }
    // Spref planes: straight 16B copies of [d][n] bf16
#pragma unroll
    for (int it = 0; it < 4; it++) {
        int idx = tid + it * 256;                 // 1024 uint4 per plane
        int ch = idx & 7, d = idx >> 3;
        size_t sbase = (size_t)blk * 8192 + (size_t)d * 64 + ch * 8;
        *(uint4*)(Sh + d * S64 + ch * 8) = *(const uint4*)(g_sph + sbase);
        *(uint4*)(Sl + d * S64 + ch * 8) = *(const uint4*)(g_spl + sbase);
    }
    // V^T [d][u], pairs along u
#pragma unroll
    for (int it = 0; it < 32; it++) {
        int idx = tid + it * 256;                 // 8192
        int d = idx & 127, u2 = idx >> 7;
        float f0 = Vb[(size_t)(2 * u2)     * D_ + d];
        float f1 = Vb[(size_t)(2 * u2 + 1) * D_ + d];
        uint32_t hi, lo; split2(f0, f1, hi, lo);
        *(uint32_t*)(Vh + d * S128 + 2 * u2) = hi;
        *(uint32_t*)(Vl + d * S128 + 2 * u2) = lo;
    }
    __syncthreads();

    const int Lm = L & 15;
    const uint32_t aQA  = smem_u32(Qh + (16 * w + Lm) * S64 + ((L >> 4) << 3));
    const uint32_t aQB  = smem_u32(Qh + (Lm & 7) * S64 + ((Lm >> 3) << 3));
    const uint32_t aSB  = smem_u32(Sh + (Lm & 7) * S64 + ((Lm >> 3) << 3));
    const uint32_t aVB  = smem_u32(Vh + (Lm & 7) * S128 + ((Lm >> 3) << 3));
    const uint32_t QOFF = 128 * S64 * 2;     // hi -> lo plane (bytes)
    const uint32_t SOFF = 128 * S64 * 2;
    const uint32_t VOFF = 128 * S128 * 2;

    // ---- Phase 1: scores = Q Q^T (K = 64) ----
    float sc[16][4];
#pragma unroll
    for (int j = 0; j < 16; j++)
#pragma unroll
        for (int q = 0; q < 4; q++) sc[j][q] = 0.f;

#pragma unroll
    for (int kk = 0; kk < 4; kk++) {
        uint32_t ah[4], al[4];
        ldmx4(ah, aQA + kk * 32);
        ldmx4(al, aQA + QOFF + kk * 32);
#pragma unroll
        for (int j = 0; j < 16; j++) {
            uint32_t bhr[2], blr[2];
            uint32_t ab = aQB + j * (8 * S64 * 2) + kk * 32;
            ldmx2(bhr, ab);
            ldmx2(blr, ab + QOFF);
            mma(sc[j], ah, bhr);
            mma(sc[j], ah, blr);
            mma(sc[j], al, bhr);
        }
    }

    // ---- mask (strict tril) + convert to A-fragments for phase 3 ----
    const int r0 = 16 * w + (L >> 2);
    uint32_t PAh[8][4], PAl[8][4];
#pragma unroll
    for (int j = 0; j < 16; j++) {
        int u0 = 8 * j + (L & 3) * 2;
        float x0 = (u0     < r0)     ? sc[j][0] : 0.f;
        float x1 = (u0 + 1 < r0)     ? sc[j][1] : 0.f;
        float x2 = (u0     < r0 + 8) ? sc[j][2] : 0.f;
        float x3 = (u0 + 1 < r0 + 8) ? sc[j][3] : 0.f;
        uint32_t h01, l01, h23, l23;
        split2(x0, x1, h01, l01);
        split2(x2, x3, h23, l23);
        PAh[j >> 1][(j & 1) * 2 + 0] = h01;
        PAh[j >> 1][(j & 1) * 2 + 1] = h23;
        PAl[j >> 1][(j & 1) * 2 + 0] = l01;
        PAl[j >> 1][(j & 1) * 2 + 1] = l23;
    }

    // ---- Phase 2: out = Q @ Spref (K = 64) ----
    float o[16][4];
#pragma unroll
    for (int j = 0; j < 16; j++)
#pragma unroll
        for (int q = 0; q < 4; q++) o[j][q] = 0.f;

#pragma unroll
    for (int kk = 0; kk < 4; kk++) {
        uint32_t ah[4], al[4];
        ldmx4(ah, aQA + kk * 32);
        ldmx4(al, aQA + QOFF + kk * 32);
#pragma unroll
        for (int j = 0; j < 16; j++) {
            uint32_t bhr[2], blr[2];
            uint32_t ab = aSB + j * (8 * S64 * 2) + kk * 32;
            ldmx2(bhr, ab);
            ldmx2(blr, ab + SOFF);
            mma(o[j], ah, bhr);
            mma(o[j], ah, blr);
            mma(o[j], al, bhr);
        }
    }

    // ---- Phase 3: out += scores @ V (K = 128, A from registers) ----
#pragma unroll
    for (int kk = 0; kk < 8; kk++) {
#pragma unroll
        for (int j = 0; j < 16; j++) {
            uint32_t bhr[2], blr[2];
            uint32_t ab = aVB + j * (8 * S128 * 2) + kk * 32;
            ldmx2(bhr, ab);
            ldmx2(blr, ab + VOFF);
            mma(o[j], PAh[kk], bhr);
            mma(o[j], PAh[kk], blr);
            mma(o[j], PAl[kk], bhr);
        }
    }

    // ---- store out[t][d] ----
    const int tg = b * T_ + k * C_;
#pragma unroll
    for (int j = 0; j < 16; j++) {
        int d0 = 8 * j + (L & 3) * 2;
        *(float2*)(out + ((size_t)(tg + r0) * NH_ + h) * D_ + d0) =
            make_float2(o[j][0], o[j][1]);
        *(float2*)(out + ((size_t)(tg + r0 + 8) * NH_ + h) * D_ + d0) =
            make_float2(o[j][2], o[j][3]);
    }
}

// ---------------------------------------------------------------------------
extern "C" void kernel_launch(void* const* d_in, const int* in_sizes, int n_in,
                              void* d_out, int out_size) {
    const float* Q     = (const float*)d_in[0];
    const float* V     = (const float*)d_in[1];
    const float* state = (const float*)d_in[2];
    float* out = (float*)d_out;

    cudaFuncSetAttribute(kA, cudaFuncAttributeMaxDynamicSharedMemorySize, (int)KA_SMEM);
    cudaFuncSetAttribute(kC, cudaFuncAttributeMaxDynamicSharedMemorySize, (int)KC_SMEM);

    bool write_state = (out_size >= (OUT_ELEMS + ST_ELEMS));
    float* out_state = write_state ? (out + OUT_ELEMS) : nullptr;

    kA<<<B_ * NH_ * NC_, 256, KA_SMEM>>>(Q, V);
    kB<<<ST_ELEMS / 256, 256>>>(state, out_state);
    kC<<<B_ * NH_ * NC_, 256, KC_SMEM>>>(Q, V, out);
}

// round 6
// speedup vs baseline: 2.6632x; 1.0763x over previous
#include <cuda_runtime.h>
#include <cuda_bf16.h>
#include <cstdint>

// Problem constants (fixed by the dataset)
#define B_  4
#define T_  2048
#define NH_ 8
#define N_  64
#define D_  128
#define C_  128          // chunk length
#define NC_ 16           // T_/C_
#define OUT_ELEMS (B_*T_*NH_*D_)   // 8,388,608
#define ST_ELEMS  (B_*NH_*N_*D_)   // 262,144

// Scratch:
//  g_dS        : per-chunk delta-state, layout [bh*16+k][d][n] fp32
//  g_sph/g_spl : prefix state (state + sum_{j<k} dS_j), bf16 hi/lo planes, [blk][d][n]
__device__ float         g_dS [(size_t)512*8192];
__device__ __nv_bfloat16 g_sph[(size_t)512*8192];
__device__ __nv_bfloat16 g_spl[(size_t)512*8192];

// ---------------------------------------------------------------------------
// helpers
// ---------------------------------------------------------------------------
__device__ __forceinline__ uint32_t smem_u32(const void* p) {
    uint32_t a;
    asm("{ .reg .u64 t; cvta.to.shared.u64 t, %1; cvt.u32.u64 %0, t; }"
        : "=r"(a) : "l"(p));
    return a;
}
__device__ __forceinline__ void ldmx4(uint32_t* r, uint32_t a) {
    asm volatile("ldmatrix.sync.aligned.m8n8.x4.shared.b16 {%0,%1,%2,%3}, [%4];"
                 : "=r"(r[0]), "=r"(r[1]), "=r"(r[2]), "=r"(r[3]) : "r"(a));
}
__device__ __forceinline__ void ldmx4t(uint32_t* r, uint32_t a) {
    asm volatile("ldmatrix.sync.aligned.m8n8.x4.trans.shared.b16 {%0,%1,%2,%3}, [%4];"
                 : "=r"(r[0]), "=r"(r[1]), "=r"(r[2]), "=r"(r[3]) : "r"(a));
}
// D += A * B, m16n8k16, row.col, bf16 in / fp32 accum
__device__ __forceinline__ void mma(float* d, const uint32_t* a, const uint32_t* b) {
    asm volatile("mma.sync.aligned.m16n8k16.row.col.f32.bf16.bf16.f32 "
                 "{%0,%1,%2,%3}, {%4,%5,%6,%7}, {%8,%9}, {%0,%1,%2,%3};"
                 : "+f"(d[0]), "+f"(d[1]), "+f"(d[2]), "+f"(d[3])
                 : "r"(a[0]), "r"(a[1]), "r"(a[2]), "r"(a[3]),
                   "r"(b[0]), "r"(b[1]));
}
// fp32 pair -> packed bf16x2 hi plane + residual lo plane (a in low half)
__device__ __forceinline__ void split2(float a, float b, uint32_t& hi, uint32_t& lo) {
    __nv_bfloat16 ha = __float2bfloat16_rn(a);
    __nv_bfloat16 hb = __float2bfloat16_rn(b);
    __nv_bfloat16 la = __float2bfloat16_rn(a - __bfloat162float(ha));
    __nv_bfloat16 lb = __float2bfloat16_rn(b - __bfloat162float(hb));
    hi = (uint32_t)__bfloat16_as_ushort(ha) | ((uint32_t)__bfloat16_as_ushort(hb) << 16);
    lo = (uint32_t)__bfloat16_as_ushort(la) | ((uint32_t)__bfloat16_as_ushort(lb) << 16);
}

// padded row strides (elements): 4-bank row offset -> conflict-free ldmatrix
#define S64  72     // rows of 64 bf16
#define S128 136    // rows of 128 bf16

// ============================================================================
// Kernel A: dS^T[d][n] = sum_c V[c][d] * Q[c][n]
//   smem: V natural [c=128][d=128] hi/lo ; Q natural [c=128][n=64] hi/lo
//   A = V^T via ldmatrix.trans ; B = Q^T via ldmatrix.trans (plane-mixed x4)
// grid = 512 (bh*16+k), 256 threads, 2 CTAs/SM
// ============================================================================
#define KA_SMEM ((size_t)(2*128*S128 + 2*128*S64)*2)   // 106,496 B

__global__ __launch_bounds__(256, 2) void kA(const float* __restrict__ Q,
                                             const float* __restrict__ V) {
    extern __shared__ __nv_bfloat16 sm[];
    __nv_bfloat16* Vh = sm;                  // [128][S128]
    __nv_bfloat16* Vl = Vh + 128 * S128;
    __nv_bfloat16* Qh = Vl + 128 * S128;     // [128][S64]
    __nv_bfloat16* Ql = Qh + 128 * S64;

    const int tid = threadIdx.x, w = tid >> 5, L = tid & 31;
    const int blk = blockIdx.x;
    const int k = blk & 15, bh = blk >> 4;
    const int b = bh >> 3, h = bh & 7;

    const float* Qb = Q + ((size_t)(b * T_ + k * C_) * NH_ + h) * N_;
    const float* Vb = V + (size_t)(b * T_ + k * C_) * D_;

    // Q natural [c][n]: coalesced float4 loads
#pragma unroll
    for (int it = 0; it < 8; it++) {
        int idx = tid + it * 256;                 // 2048 float4
        int n4 = idx & 15, c = idx >> 4;
        float4 q = *(const float4*)(Qb + (size_t)c * (NH_ * N_) + n4 * 4);
        uint32_t h0, l0, h1, l1;
        split2(q.x, q.y, h0, l0);
        split2(q.z, q.w, h1, l1);
        *(uint2*)(Qh + c * S64 + n4 * 4) = make_uint2(h0, h1);
        *(uint2*)(Ql + c * S64 + n4 * 4) = make_uint2(l0, l1);
    }
    // V natural [c][d]
#pragma unroll
    for (int it = 0; it < 16; it++) {
        int idx = tid + it * 256;                 // 4096 float4
        int d4 = idx & 31, c = idx >> 5;
        float4 v = *(const float4*)(Vb + (size_t)c * D_ + d4 * 4);
        uint32_t h0, l0, h1, l1;
        split2(v.x, v.y, h0, l0);
        split2(v.z, v.w, h1, l1);
        *(uint2*)(Vh + c * S128 + d4 * 4) = make_uint2(h0, h1);
        *(uint2*)(Vl + c * S128 + d4 * 4) = make_uint2(l0, l1);
    }
    __syncthreads();

    // A (V^T, m=d block 16w..16w+15) trans x4: lanes 0-7: c0-7/m, 8-15: c0-7/m+8,
    // 16-23: c8-15/m, 24-31: c8-15/m+8
    const uint32_t aA = smem_u32(
        Vh + ((L & 7) + ((L >> 4) << 3)) * S128 + 16 * w + (((L >> 3) & 1) << 3));
    const uint32_t VPL = 128 * S128 * 2;          // hi->lo plane (bytes)
    // B (Q^T) trans x4 plane-mixed: lanes 0-15 hi rows c0-15, lanes 16-31 lo
    const uint32_t aB = smem_u32((L < 16 ? Qh : Ql) + (L & 15) * S64);

    float acc[8][4];
#pragma unroll
    for (int j = 0; j < 8; j++)
#pragma unroll
        for (int q = 0; q < 4; q++) acc[j][q] = 0.f;

#pragma unroll
    for (int kk = 0; kk < 8; kk++) {
        uint32_t ah[4], al[4];
        ldmx4t(ah, aA + kk * (16 * S128 * 2));
        ldmx4t(al, aA + VPL + kk * (16 * S128 * 2));
#pragma unroll
        for (int j = 0; j < 8; j++) {
            uint32_t br[4];   // {bh0, bh1, bl0, bl1}
            ldmx4t(br, aB + kk * (16 * S64 * 2) + j * 16);
            mma(acc[j], ah, br);
            mma(acc[j], ah, br + 2);
            mma(acc[j], al, br);
        }
    }

    const int r0 = 16 * w + (L >> 2);
    const int cc = (L & 3) * 2;
    float* op = g_dS + (size_t)blk * 8192;
#pragma unroll
    for (int j = 0; j < 8; j++) {
        *(float2*)(op + (size_t)r0 * 64 + 8 * j + cc)       = make_float2(acc[j][0], acc[j][1]);
        *(float2*)(op + (size_t)(r0 + 8) * 64 + 8 * j + cc) = make_float2(acc[j][2], acc[j][3]);
    }
}

// ============================================================================
// Kernel B: exclusive prefix over the 16 chunks -> bf16 hi/lo planes + new_state
// ============================================================================
__global__ void kB(const float* __restrict__ state, float* __restrict__ out_state) {
    int gid = blockIdx.x * 256 + threadIdx.x;       // < 262144
    int bh = gid >> 13, dn = gid & 8191;
    int d = dn >> 6, n = dn & 63;
    const size_t base = (size_t)bh * NC_ * 8192 + dn;
    float run = state[((size_t)bh * 64 + n) * 128 + d];
#pragma unroll
    for (int k = 0; k < NC_; k++) {
        float v = g_dS[base + (size_t)k * 8192];
        __nv_bfloat16 hh = __float2bfloat16_rn(run);
        __nv_bfloat16 ll = __float2bfloat16_rn(run - __bfloat162float(hh));
        g_sph[base + (size_t)k * 8192] = hh;
        g_spl[base + (size_t)k * 8192] = ll;
        run += v;
    }
    if (out_state) out_state[((size_t)bh * 64 + n) * 128 + d] = run;
}

// ============================================================================
// Kernel C: per chunk:
//   scores = tril(Q Q^T, -1)   (register accum, masked, reused as A frags)
//   out    = Q @ Spref + scores @ V
//   smem: Q natural [t][n] hi/lo ; Spref^T [d][n] hi/lo ; V natural [u][d] hi/lo
// grid = 512 blocks, 256 threads
// ============================================================================
#define KC_SMEM ((size_t)(4*128*S64 + 2*128*S128)*2)   // 143,360 B

__global__ __launch_bounds__(256) void kC(const float* __restrict__ Q,
                                          const float* __restrict__ V,
                                          float* __restrict__ out) {
    extern __shared__ __nv_bfloat16 sm[];
    __nv_bfloat16* Qh = sm;                 // [128][S64]  Q[t][n]
    __nv_bfloat16* Ql = Qh + 128 * S64;
    __nv_bfloat16* Sh = Ql + 128 * S64;     // [128][S64]  Spref^T[d][n]
    __nv_bfloat16* Sl = Sh + 128 * S64;
    __nv_bfloat16* Vh = Sl + 128 * S64;     // [128][S128] V[u][d] (natural)
    __nv_bfloat16* Vl = Vh + 128 * S128;

    const int tid = threadIdx.x, w = tid >> 5, L = tid & 31;
    const int blk = blockIdx.x;
    const int k = blk & 15, bh = blk >> 4;
    const int b = bh >> 3, h = bh & 7;

    const float* Qb = Q + ((size_t)(b * T_ + k * C_) * NH_ + h) * N_;
    const float* Vb = V + (size_t)(b * T_ + k * C_) * D_;

    // Q natural [t][n]
#pragma unroll
    for (int it = 0; it < 8; it++) {
        int idx = tid + it * 256;                 // 2048 float4
        int n4 = idx & 15, t = idx >> 4;
        float4 q = *(const float4*)(Qb + (size_t)t * (NH_ * N_) + n4 * 4);
        uint32_t h0, l0, h1, l1;
        split2(q.x, q.y, h0, l0);
        split2(q.z, q.w, h1, l1);
        *(uint2*)(Qh + t * S64 + n4 * 4) = make_uint2(h0, h1);
        *(uint2*)(Ql + t * S64 + n4 * 4) = make_uint2(l0, l1);
    }
    // Spref planes: straight 16B copies of [d][n] bf16
#pragma unroll
    for (int it = 0; it < 4; it++) {
        int idx = tid + it * 256;                 // 1024 uint4 per plane
        int ch = idx & 7, d = idx >> 3;
        size_t sbase = (size_t)blk * 8192 + (size_t)d * 64 + ch * 8;
        *(uint4*)(Sh + d * S64 + ch * 8) = *(const uint4*)(g_sph + sbase);
        *(uint4*)(Sl + d * S64 + ch * 8) = *(const uint4*)(g_spl + sbase);
    }
    // V natural [u][d]
#pragma unroll
    for (int it = 0; it < 16; it++) {
        int idx = tid + it * 256;                 // 4096 float4
        int d4 = idx & 31, u = idx >> 5;
        float4 v = *(const float4*)(Vb + (size_t)u * D_ + d4 * 4);
        uint32_t h0, l0, h1, l1;
        split2(v.x, v.y, h0, l0);
        split2(v.z, v.w, h1, l1);
        *(uint2*)(Vh + u * S128 + d4 * 4) = make_uint2(h0, h1);
        *(uint2*)(Vl + u * S128 + d4 * 4) = make_uint2(l0, l1);
    }
    __syncthreads();

    const int Lm = L & 15;
    // A (Q rows 16w..16w+15) non-trans x4 (per plane)
    const uint32_t aQA = smem_u32(Qh + (16 * w + Lm) * S64 + ((L >> 4) << 3));
    const uint32_t QOFF = 128 * S64 * 2;     // hi -> lo plane (bytes)
    // B non-trans plane-mixed x4: lanes 0-15 hi (rows j*8+(L&7), col-half (L>>3)&1),
    // lanes 16-31 lo
    const uint32_t aQB = smem_u32((L < 16 ? Qh : Ql) + (L & 7) * S64 + (((L >> 3) & 1) << 3));
    const uint32_t aSB = smem_u32((L < 16 ? Sh : Sl) + (L & 7) * S64 + (((L >> 3) & 1) << 3));
    // B (V^T) trans plane-mixed x4: lanes 0-15 hi rows u0-15, lanes 16-31 lo
    const uint32_t aVB = smem_u32((L < 16 ? Vh : Vl) + (L & 15) * S128);

    // ---- Phase 1: scores = Q Q^T (K = 64) ----
    float sc[16][4];
#pragma unroll
    for (int j = 0; j < 16; j++)
#pragma unroll
        for (int q = 0; q < 4; q++) sc[j][q] = 0.f;

#pragma unroll
    for (int kk = 0; kk < 4; kk++) {
        uint32_t ah[4], al[4];
        ldmx4(ah, aQA + kk * 32);
        ldmx4(al, aQA + QOFF + kk * 32);
#pragma unroll
        for (int j = 0; j < 16; j++) {
            uint32_t br[4];
            ldmx4(br, aQB + j * (8 * S64 * 2) + kk * 32);
            mma(sc[j], ah, br);
            mma(sc[j], ah, br + 2);
            mma(sc[j], al, br);
        }
    }

    // ---- mask (strict tril) + convert to A-fragments for phase 3 ----
    const int r0 = 16 * w + (L >> 2);
    uint32_t PAh[8][4], PAl[8][4];
#pragma unroll
    for (int j = 0; j < 16; j++) {
        int u0 = 8 * j + (L & 3) * 2;
        float x0 = (u0     < r0)     ? sc[j][0] : 0.f;
        float x1 = (u0 + 1 < r0)     ? sc[j][1] : 0.f;
        float x2 = (u0     < r0 + 8) ? sc[j][2] : 0.f;
        float x3 = (u0 + 1 < r0 + 8) ? sc[j][3] : 0.f;
        uint32_t h01, l01, h23, l23;
        split2(x0, x1, h01, l01);
        split2(x2, x3, h23, l23);
        PAh[j >> 1][(j & 1) * 2 + 0] = h01;
        PAh[j >> 1][(j & 1) * 2 + 1] = h23;
        PAl[j >> 1][(j & 1) * 2 + 0] = l01;
        PAl[j >> 1][(j & 1) * 2 + 1] = l23;
    }

    // ---- Phase 2: out = Q @ Spref (K = 64) ----
    float o[16][4];
#pragma unroll
    for (int j = 0; j < 16; j++)
#pragma unroll
        for (int q = 0; q < 4; q++) o[j][q] = 0.f;

#pragma unroll
    for (int kk = 0; kk < 4; kk++) {
        uint32_t ah[4], al[4];
        ldmx4(ah, aQA + kk * 32);
        ldmx4(al, aQA + QOFF + kk * 32);
#pragma unroll
        for (int j = 0; j < 16; j++) {
            uint32_t br[4];
            ldmx4(br, aSB + j * (8 * S64 * 2) + kk * 32);
            mma(o[j], ah, br);
            mma(o[j], ah, br + 2);
            mma(o[j], al, br);
        }
    }

    // ---- Phase 3: out += scores @ V (K = 128, A from registers) ----
#pragma unroll
    for (int kk = 0; kk < 8; kk++) {
#pragma unroll
        for (int j = 0; j < 16; j++) {
            uint32_t br[4];
            ldmx4t(br, aVB + kk * (16 * S128 * 2) + j * 16);
            mma(o[j], PAh[kk], br);
            mma(o[j], PAh[kk], br + 2);
            mma(o[j], PAl[kk], br);
        }
    }

    // ---- store out[t][d] ----
    const int tg = b * T_ + k * C_;
#pragma unroll
    for (int j = 0; j < 16; j++) {
        int d0 = 8 * j + (L & 3) * 2;
        *(float2*)(out + ((size_t)(tg + r0) * NH_ + h) * D_ + d0) =
            make_float2(o[j][0], o[j][1]);
        *(float2*)(out + ((size_t)(tg + r0 + 8) * NH_ + h) * D_ + d0) =
            make_float2(o[j][2], o[j][3]);
    }
}

// ---------------------------------------------------------------------------
extern "C" void kernel_launch(void* const* d_in, const int* in_sizes, int n_in,
                              void* d_out, int out_size) {
    const float* Q     = (const float*)d_in[0];
    const float* V     = (const float*)d_in[1];
    const float* state = (const float*)d_in[2];
    float* out = (float*)d_out;

    cudaFuncSetAttribute(kA, cudaFuncAttributeMaxDynamicSharedMemorySize, (int)KA_SMEM);
    cudaFuncSetAttribute(kC, cudaFuncAttributeMaxDynamicSharedMemorySize, (int)KC_SMEM);

    bool write_state = (out_size >= (OUT_ELEMS + ST_ELEMS));
    float* out_state = write_state ? (out + OUT_ELEMS) : nullptr;

    kA<<<B_ * NH_ * NC_, 256, KA_SMEM>>>(Q, V);
    kB<<<ST_ELEMS / 256, 256>>>(state, out_state);
    kC<<<B_ * NH_ * NC_, 256, KC_SMEM>>>(Q, V, out);
}